// round 6
// baseline (speedup 1.0000x reference)
#include <cuda_runtime.h>
#include <math.h>

#define BS 2
#define NF 8
#define NQ 300
#define HH 96
#define WW 96
#define HW (HH*WW)           // 9216
#define DTOT (NF*HW)         // 73728 per batch
#define WPR 3                // 3 uint32 words per 96-col row
#define NBLK (BS*NQ*NF)      // 4800 main blocks
#define LN2F 0.6931471805599453f

// ---------------- device scratch (no allocations allowed) ----------------
__device__ unsigned g_tbits[BS*NF*HH*WPR];  // target mask bits per (b,f): 288 words
__device__ unsigned g_pbits[BS*HH*WPR];     // pad bits per b: 288 words
__device__ float g_trm  [BS*NF*WW];         // target max over h, per w  (tgt_y)
__device__ float g_tcm  [BS*NF*HH];         // target max over w, per h  (tgt_x)
__device__ float g_tscal[BS*NF*4];          // {tsum, sum(trm)=TTY, sum(tcm)=TTX, -}
__device__ float g_rec  [BS*NQ*NF*8];       // {focal, thsum, thsum_pos, sx, stx, sy, sty, -}
__device__ unsigned g_count = 0;            // completion counter for fused epilogue

__device__ __forceinline__ float sigf(float x){
    float e   = __expf(-fabsf(x));
    float inv = __fdividef(1.f, 1.f + e);
    return (x >= 0.f) ? inv : 1.f - inv;
}
__device__ __forceinline__ float tanh_approx(float x){
    float r; asm("tanh.approx.f32 %0, %1;" : "=f"(r) : "f"(x)); return r;
}

// ---------------- kernel A: target reductions + bit packing ----------------
__global__ __launch_bounds__(256) void tgt_kernel(const float* __restrict__ tmask,
                                                  const unsigned char* __restrict__ pad){
    int b = blockIdx.x / NF, f = blockIdx.x % NF;
    int bf = b*NF + f;
    int tid = threadIdx.x, lane = tid & 31, wid = tid >> 5;  // 8 warps

    if (blockIdx.x == 0 && tid == 0) g_count = 0;  // safety reset

    __shared__ float tile[HH*97];
    __shared__ float sred[8][3];

    // coalesced load of the 36 KB target tile
    const float4* tm4 = (const float4*)(tmask + (size_t)bf*HW);
    for (int i = tid; i < HH*24; i += 256){
        int r = i / 24, c = i % 24;
        float4 v = tm4[i];
        tile[r*97 + 4*c+0] = v.x; tile[r*97 + 4*c+1] = v.y;
        tile[r*97 + 4*c+2] = v.z; tile[r*97 + 4*c+3] = v.w;
    }
    __syncthreads();

    // target bit packing: warp w handles rows [12w, 12w+12)
    for (int rr = 0; rr < 12; rr++){
        int r = wid*12 + rr;
        #pragma unroll
        for (int w3 = 0; w3 < 3; w3++){
            unsigned ball = __ballot_sync(0xffffffffu, tile[r*97 + w3*32 + lane] > 0.5f);
            if (lane == 0) g_tbits[bf*HH*WPR + r*WPR + w3] = ball;
        }
    }

    // pad bit packing (only f==0 block per b)
    if (f == 0){
        const unsigned char* pd = pad + (size_t)b*HW;
        for (int rr = 0; rr < 12; rr++){
            int r = wid*12 + rr;
            #pragma unroll
            for (int w3 = 0; w3 < 3; w3++){
                unsigned ball = __ballot_sync(0xffffffffu, pd[r*WW + w3*32 + lane] != 0);
                if (lane == 0) g_pbits[b*HH*WPR + r*WPR + w3] = ball;
            }
        }
    }

    // column maxima (max over h, per w) + total sum ; row maxima (max over w, per h)
    float va = 0.f, vb = 0.f, vc = 0.f;
    if (tid < 96){
        float m = -INFINITY, s = 0.f;
        for (int h = 0; h < HH; h++){
            float v = tile[h*97 + tid];
            m = fmaxf(m, v); s += v;
        }
        g_trm[bf*WW + tid] = m;
        va = s; vb = m;
    } else if (tid < 192){
        int h = tid - 96;
        float m2 = -INFINITY;
        for (int w = 0; w < WW; w++) m2 = fmaxf(m2, tile[h*97 + w]);
        g_tcm[bf*HH + h] = m2;
        vc = m2;
    }
    #pragma unroll
    for (int off = 16; off; off >>= 1){
        va += __shfl_down_sync(0xffffffffu, va, off);
        vb += __shfl_down_sync(0xffffffffu, vb, off);
        vc += __shfl_down_sync(0xffffffffu, vc, off);
    }
    if (lane == 0){ sred[wid][0] = va; sred[wid][1] = vb; sred[wid][2] = vc; }
    __syncthreads();
    if (tid == 0){
        float s0=0, s1=0, s2=0;
        #pragma unroll
        for (int w = 0; w < 8; w++){ s0 += sred[w][0]; s1 += sred[w][1]; s2 += sred[w][2]; }
        g_tscal[bf*4+0] = s0;   // tsum (count of positives)
        g_tscal[bf*4+1] = s1;   // TTY = sum of per-w maxima
        g_tscal[bf*4+2] = s2;   // TTX = sum of per-h maxima
    }
}

// ---------------- epilogue helper: full cost for one (b,q) ----------------
__device__ float cost_pair(int b, int q,
                           const float* __restrict__ logits,
                           const float* __restrict__ boxes,
                           const float* __restrict__ tbox,
                           const int*   __restrict__ tvalid)
{
    float F=0, TH=0, THP=0, SX=0, STX=0, SY=0, STY=0;
    float TS=0, TTY=0, TTX=0, wsum=0, cc=0, bbsum=0, gsum=0;
    #pragma unroll
    for (int f = 0; f < NF; f++){
        int bf = b*NF + f;
        const float* rec = &g_rec[((size_t)(b*NQ + q)*NF + f)*8];
        F   += rec[0]; TH  += rec[1]; THP += rec[2];
        SX  += rec[3]; STX += rec[4]; SY  += rec[5]; STY += rec[6];
        TS  += g_tscal[bf*4+0];
        TTY += g_tscal[bf*4+1];
        TTX += g_tscal[bf*4+2];

        float wf = (tvalid[bf] != 0) ? 1.f : 0.f;
        wsum += wf;
        float lg = logits[bf*NQ + q];
        float pp;
        if (lg >= 0.f){ float e = expf(-lg); pp = 1.f/(1.f+e); }
        else          { float e = expf( lg); pp = e/(1.f+e); }
        float pos = 0.25f*(1.f-pp)*(1.f-pp)*(-logf(pp + 1e-8f));
        float neg = 0.75f*pp*pp*(-logf(1.f - pp + 1e-8f));
        cc += (pos - neg)*wf;

        const float* sb = boxes + (size_t)(bf*NQ + q)*4;
        const float* tb = tbox  + (size_t)bf*4;
        float scx=sb[0], scy=sb[1], sw=sb[2], sh=sb[3];
        float tcx=tb[0], tcy=tb[1], tw=tb[2], th=tb[3];
        bbsum += fabsf(scx-tcx) + fabsf(scy-tcy) + fabsf(sw-tw) + fabsf(sh-th);

        float sx0=scx-0.5f*sw, sy0=scy-0.5f*sh, sx1=scx+0.5f*sw, sy1=scy+0.5f*sh;
        float tx0=tcx-0.5f*tw, ty0=tcy-0.5f*th, tx1=tcx+0.5f*tw, ty1=tcy+0.5f*th;
        float a1=(sx1-sx0)*(sy1-sy0);
        float a2=(tx1-tx0)*(ty1-ty0);
        float ltx=fmaxf(sx0,tx0), lty=fmaxf(sy0,ty0);
        float rbx=fminf(sx1,tx1), rby=fminf(sy1,ty1);
        float iw=fmaxf(rbx-ltx,0.f), ih=fmaxf(rby-lty,0.f);
        float inter=iw*ih;
        float uni=a1+a2-inter;
        float iou=inter/uni;
        float cx0=fminf(sx0,tx0), cy0=fminf(sy0,ty0);
        float cx1=fmaxf(sx1,tx1), cy1=fmaxf(sy1,ty1);
        float cw=fmaxf(cx1-cx0,0.f), ch=fmaxf(cy1-cy0,0.f);
        float ac=cw*ch;
        gsum += iou - (ac-uni)/ac;
    }
    // reconstruct sigmoid sums from tanh sums
    float S  = 0.5f*(float)DTOT + 0.5f*TH;
    float ST = 0.5f*TS + 0.5f*THP;
    float cost_mask = F / (float)DTOT;
    float cost_dice = -(2.f*ST + 1.f) / (S + TS + 1.f);
    float cost_proj = -0.5f * ( (2.f*STX + 1.f)/(SX + TTX + 1.f)
                              + (2.f*STY + 1.f)/(SY + TTY + 1.f) );
    float cost_class = cc / wsum;
    float cost_bbox  = bbsum / (float)NF;
    float cost_giou  = -gsum / (float)NF;
    return cost_class + cost_bbox + cost_giou + cost_mask + cost_dice + cost_proj;
}

// ---------------- kernel B: fused streaming pass + epilogue ----------------
__global__ __launch_bounds__(288) void main_kernel(
    const float* __restrict__ masks,
    const float* __restrict__ logits,
    const float* __restrict__ boxes,
    const float* __restrict__ tbox,
    const int*   __restrict__ tvalid,
    float* __restrict__ outf, int out_size)
{
    int bx  = blockIdx.x;              // b*NQ*NF + q*NF + f
    int b   = bx / (NQ*NF);
    int rem = bx % (NQ*NF);
    int q   = rem / NF;
    int f   = rem % NF;
    int bf  = b*NF + f;

    const float4* xm = (const float4*)(masks + ((size_t)(bf*NQ + q))*HW);

    __shared__ float    rowpart[HH*25];
    __shared__ float    colpart[12*WW];
    __shared__ unsigned sh_t[HH*WPR];
    __shared__ unsigned sh_p[HH*WPR];
    __shared__ float    red[9*3];
    __shared__ float    red2[6][2];
    __shared__ int      isLast;
    __shared__ float    sC[BS*NQ];
    __shared__ float    avm[9];
    __shared__ int      aim[9];

    int tid = threadIdx.x;
    sh_t[tid] = g_tbits[bf*HH*WPR + tid];
    sh_p[tid] = g_pbits[b *HH*WPR + tid];
    __syncthreads();

    int fc = tid % 24;                 // float4 column
    int r0 = tid / 24;                 // 0..11
    int wi = fc >> 3;                  // bit-word within row
    int shb = (4*fc) & 31;

    float cmax0=-INFINITY, cmax1=-INFINITY, cmax2=-INFINITY, cmax3=-INFINITY;
    float focal = 0.f, thsum = 0.f, thp = 0.f;

    #pragma unroll
    for (int k = 0; k < 8; k++){
        int r = r0 + 12*k;
        float4 x4 = xm[r*24 + fc];
        unsigned tw = sh_t[r*WPR + wi] >> shb;
        unsigned pw = sh_p[r*WPR + wi] >> shb;
        float rmax = -INFINITY;
        float xs[4] = {x4.x, x4.y, x4.z, x4.w};
        #pragma unroll
        for (int j = 0; j < 4; j++){
            float x = ((pw >> j) & 1u) ? 0.f : xs[j];
            bool tt = (tw >> j) & 1u;
            float th = tanh_approx(0.5f * x);
            thsum += th;
            if (tt) thp += th;
            float sgn = tt ? 0.5f : -0.5f;
            float pt  = fmaf(sgn, th, 0.5f);     // p_t
            float qv  = 1.f - pt;
            float l   = __log2f(fmaxf(pt, 1e-12f));
            float c2  = tt ? (-0.25f*LN2F) : (-0.75f*LN2F);
            focal = fmaf(c2*l, qv*qv, focal);    // alpha_t*ce*(1-p_t)^2
            rmax = fmaxf(rmax, x);
            if      (j == 0) cmax0 = fmaxf(cmax0, x);
            else if (j == 1) cmax1 = fmaxf(cmax1, x);
            else if (j == 2) cmax2 = fmaxf(cmax2, x);
            else             cmax3 = fmaxf(cmax3, x);
        }
        rowpart[r*25 + fc] = rmax;
    }
    ((float4*)colpart)[r0*24 + fc] = make_float4(cmax0, cmax1, cmax2, cmax3);

    #pragma unroll
    for (int off = 16; off; off >>= 1){
        focal += __shfl_down_sync(0xffffffffu, focal, off);
        thsum += __shfl_down_sync(0xffffffffu, thsum, off);
        thp   += __shfl_down_sync(0xffffffffu, thp,   off);
    }
    int wid = tid >> 5, lane = tid & 31;
    if (lane == 0){ red[wid*3] = focal; red[wid*3+1] = thsum; red[wid*3+2] = thp; }
    __syncthreads();

    // projection partial sums
    float a = 0.f, bsum = 0.f;
    if (tid < 96){
        int h = tid; float m = -INFINITY;
        #pragma unroll 8
        for (int c = 0; c < 24; c++) m = fmaxf(m, rowpart[h*25 + c]);
        float sp = sigf(m);
        a = sp; bsum = sp * __ldg(&g_tcm[bf*HH + h]);
    } else if (tid < 192){
        int w = tid - 96; float m = -INFINITY;
        #pragma unroll 4
        for (int r = 0; r < 12; r++) m = fmaxf(m, colpart[r*WW + w]);
        float sp = sigf(m);
        a = sp; bsum = sp * __ldg(&g_trm[bf*WW + w]);
    }
    if (tid < 192){
        #pragma unroll
        for (int off = 16; off; off >>= 1){
            a    += __shfl_down_sync(0xffffffffu, a,    off);
            bsum += __shfl_down_sync(0xffffffffu, bsum, off);
        }
        if (lane == 0){ red2[wid][0] = a; red2[wid][1] = bsum; }
    }
    __syncthreads();

    if (tid == 0){
        float F=0,TH=0,TP=0;
        #pragma unroll
        for (int w = 0; w < 9; w++){ F += red[w*3]; TH += red[w*3+1]; TP += red[w*3+2]; }
        float sx  = red2[0][0]+red2[1][0]+red2[2][0];
        float stx = red2[0][1]+red2[1][1]+red2[2][1];
        float sy  = red2[3][0]+red2[4][0]+red2[5][0];
        float sty = red2[3][1]+red2[4][1]+red2[5][1];
        float* rec = &g_rec[((size_t)(b*NQ + q)*NF + f)*8];
        rec[0]=F; rec[1]=TH; rec[2]=TP; rec[3]=sx; rec[4]=stx; rec[5]=sy; rec[6]=sty;
    }

    // ---------------- last-block epilogue: cost matrix + argmin ----------------
    if (tid == 0){
        __threadfence();
        unsigned prev = atomicAdd(&g_count, 1u);
        isLast = (prev == (unsigned)(NBLK - 1));
    }
    __syncthreads();
    if (!isLast) return;
    __threadfence();

    for (int i = tid; i < BS*NQ; i += 288){
        int bb2 = i / NQ, qq = i % NQ;
        float c = cost_pair(bb2, qq, logits, boxes, tbox, tvalid);
        sC[i] = c;
        outf[i] = c;
    }
    __syncthreads();

    for (int bb2 = 0; bb2 < BS; bb2++){
        float v = sC[bb2*NQ + tid]; int idx = tid;   // tid < 288 < 300 always valid
        if (tid + 288 < NQ){
            float v2 = sC[bb2*NQ + tid + 288];
            if (v2 < v){ v = v2; idx = tid + 288; }
        }
        #pragma unroll
        for (int off = 16; off; off >>= 1){
            float v2 = __shfl_down_sync(0xffffffffu, v, off);
            int   i2 = __shfl_down_sync(0xffffffffu, idx, off);
            if (v2 < v || (v2 == v && i2 < idx)){ v = v2; idx = i2; }
        }
        if (lane == 0){ avm[wid] = v; aim[wid] = idx; }
        __syncthreads();
        if (tid == 0){
            float bv = avm[0]; int bi = aim[0];
            #pragma unroll
            for (int w = 1; w < 9; w++){
                if (avm[w] < bv || (avm[w] == bv && aim[w] < bi)){ bv = avm[w]; bi = aim[w]; }
            }
            if (out_size == 608){
                long long* ip = (long long*)(outf + BS*NQ);
                ip[bb2]      = (long long)bi;  // src_ind
                ip[BS + bb2] = 0LL;            // tgt_ind
            } else if (out_size >= BS*NQ + 2*BS){
                outf[BS*NQ + bb2]      = (float)bi;
                outf[BS*NQ + BS + bb2] = 0.f;
            }
        }
        __syncthreads();
    }
    if (tid == 0) g_count = 0;   // reset for next graph replay
}

// ---------------- launch ----------------
extern "C" void kernel_launch(void* const* d_in, const int* in_sizes, int n_in,
                              void* d_out, int out_size)
{
    const float* logits = (const float*)d_in[0];
    const float* boxes  = (const float*)d_in[1];
    const float* masks  = (const float*)d_in[2];
    const float* tmask  = (const float*)d_in[3];
    const float* tbox   = (const float*)d_in[4];
    const int*   tvalid = (const int*)d_in[5];
    const unsigned char* pad = (const unsigned char*)d_in[6];
    float* outf = (float*)d_out;

    tgt_kernel <<<BS*NF,  256>>>(tmask, pad);
    main_kernel<<<NBLK,   288>>>(masks, logits, boxes, tbox, tvalid, outf, out_size);
}

// round 8
// speedup vs baseline: 1.5984x; 1.5984x over previous
#include <cuda_runtime.h>
#include <math.h>
#include <stdint.h>

#define BS 2
#define NF 8
#define NQ 300
#define HH 96
#define WW 96
#define HW (HH*WW)           // 9216
#define DTOT (NF*HW)         // 73728 per batch
#define WPR 3                // 3 uint32 words per 96-col row
#define THR 384              // 12 warps
#define NBQ (BS*NQ)          // 600 blocks
#define TILE_BYTES (HW*4)    // 36864
#define LN2F 0.6931471805599453f

// ---------------- device scratch (no allocations allowed) ----------------
__device__ unsigned g_tbits[BS*NF*HH*WPR];  // target mask bits per (b,f)
__device__ unsigned g_pbits[BS*HH*WPR];     // pad bits per b
__device__ float g_trm  [BS*NF*WW];         // target max over h, per w  (tgt_y)
__device__ float g_tcm  [BS*NF*HH];         // target max over w, per h  (tgt_x)
__device__ float g_tscal[BS*NF*4];          // {tsum, TTY=sum(trm), TTX=sum(tcm), -}
__device__ unsigned g_count = 0;

struct SmLayout {
    unsigned long long mbar[2];       // 16 B, 8-aligned
    float    buf[2][HW];              // 73728 B (16B aligned: offset 16)
    unsigned tb[NF*HH*WPR];           // 9216 B
    unsigned pb[HH*WPR];              // 1152 B
    float    rowpart[HH*25];          // 9600 B
    float    colpart[16*WW];          // 6144 B (offset 16+73728+9216+1152+9600=93712, 16B aligned)
    float    red[12*3];
    float    red2[6][2];
    float    acc[4];                  // SX, STX, SY, STY over f
    float    avm[12];
    int      aim[12];
    int      isLast;
};

__device__ __forceinline__ float sigf(float x){
    float e   = __expf(-fabsf(x));
    float inv = __fdividef(1.f, 1.f + e);
    return (x >= 0.f) ? inv : 1.f - inv;
}
__device__ __forceinline__ float tanh_approx(float x){
    float r; asm("tanh.approx.f32 %0, %1;" : "=f"(r) : "f"(x)); return r;
}
__device__ __forceinline__ unsigned smem_u32(const void* p){
    unsigned a;
    asm("{ .reg .u64 t; cvta.to.shared.u64 t, %1; cvt.u32.u64 %0, t; }" : "=r"(a) : "l"(p));
    return a;
}
__device__ __forceinline__ void mbar_init(unsigned mbar, unsigned cnt){
    asm volatile("mbarrier.init.shared.b64 [%0], %1;" :: "r"(mbar), "r"(cnt) : "memory");
}
__device__ __forceinline__ void mbar_expect_tx(unsigned mbar, unsigned bytes){
    asm volatile("mbarrier.arrive.expect_tx.shared.b64 _, [%0], %1;" :: "r"(mbar), "r"(bytes) : "memory");
}
__device__ __forceinline__ void bulk_g2s(unsigned dst, const void* src, unsigned bytes, unsigned mbar){
    asm volatile("cp.async.bulk.shared::cta.global.mbarrier::complete_tx::bytes [%0], [%1], %2, [%3];"
                 :: "r"(dst), "l"(src), "r"(bytes), "r"(mbar) : "memory");
}
__device__ __forceinline__ void mbar_wait(unsigned mbar, unsigned parity){
    asm volatile(
        "{\n\t"
        ".reg .pred P;\n\t"
        "WL_%=:\n\t"
        "mbarrier.try_wait.parity.acquire.cta.shared::cta.b64 P, [%0], %1, 0x989680;\n\t"
        "@P bra.uni WD_%=;\n\t"
        "bra.uni WL_%=;\n\t"
        "WD_%=:\n\t"
        "}"
        :: "r"(mbar), "r"(parity) : "memory");
}

// ---------------- kernel A: target reductions + bit packing ----------------
__global__ __launch_bounds__(256) void tgt_kernel(const float* __restrict__ tmask,
                                                  const unsigned char* __restrict__ pad){
    int b = blockIdx.x / NF, f = blockIdx.x % NF;
    int bf = b*NF + f;
    int tid = threadIdx.x, lane = tid & 31, wid = tid >> 5;

    if (blockIdx.x == 0 && tid == 0) g_count = 0;

    __shared__ float tile[HH*97];
    __shared__ float sred[8][3];

    const float4* tm4 = (const float4*)(tmask + (size_t)bf*HW);
    for (int i = tid; i < HH*24; i += 256){
        int r = i / 24, c = i % 24;
        float4 v = tm4[i];
        tile[r*97 + 4*c+0] = v.x; tile[r*97 + 4*c+1] = v.y;
        tile[r*97 + 4*c+2] = v.z; tile[r*97 + 4*c+3] = v.w;
    }
    __syncthreads();

    for (int rr = 0; rr < 12; rr++){
        int r = wid*12 + rr;
        #pragma unroll
        for (int w3 = 0; w3 < 3; w3++){
            unsigned ball = __ballot_sync(0xffffffffu, tile[r*97 + w3*32 + lane] > 0.5f);
            if (lane == 0) g_tbits[bf*HH*WPR + r*WPR + w3] = ball;
        }
    }
    if (f == 0){
        const unsigned char* pd = pad + (size_t)b*HW;
        for (int rr = 0; rr < 12; rr++){
            int r = wid*12 + rr;
            #pragma unroll
            for (int w3 = 0; w3 < 3; w3++){
                unsigned ball = __ballot_sync(0xffffffffu, pd[r*WW + w3*32 + lane] != 0);
                if (lane == 0) g_pbits[b*HH*WPR + r*WPR + w3] = ball;
            }
        }
    }

    float va = 0.f, vb = 0.f, vc = 0.f;
    if (tid < 96){
        float m = -INFINITY, s = 0.f;
        for (int h = 0; h < HH; h++){
            float v = tile[h*97 + tid];
            m = fmaxf(m, v); s += v;
        }
        g_trm[bf*WW + tid] = m;
        va = s; vb = m;
    } else if (tid < 192){
        int h = tid - 96;
        float m2 = -INFINITY;
        for (int w = 0; w < WW; w++) m2 = fmaxf(m2, tile[h*97 + w]);
        g_tcm[bf*HH + h] = m2;
        vc = m2;
    }
    #pragma unroll
    for (int off = 16; off; off >>= 1){
        va += __shfl_down_sync(0xffffffffu, va, off);
        vb += __shfl_down_sync(0xffffffffu, vb, off);
        vc += __shfl_down_sync(0xffffffffu, vc, off);
    }
    if (lane == 0){ sred[wid][0] = va; sred[wid][1] = vb; sred[wid][2] = vc; }
    __syncthreads();
    if (tid == 0){
        float s0=0, s1=0, s2=0;
        #pragma unroll
        for (int w = 0; w < 8; w++){ s0 += sred[w][0]; s1 += sred[w][1]; s2 += sred[w][2]; }
        g_tscal[bf*4+0] = s0; g_tscal[bf*4+1] = s1; g_tscal[bf*4+2] = s2;
    }
}

// ---------------- kernel B: one block per (b,q), cp.async.bulk pipeline ----------------
__global__ __launch_bounds__(THR, 2) void main_kernel(
    const float* __restrict__ masks,
    const float* __restrict__ logits,
    const float* __restrict__ boxes,
    const float* __restrict__ tbox,
    const int*   __restrict__ tvalid,
    float* __restrict__ outf, int out_size)
{
    extern __shared__ char smem_raw[];
    SmLayout* s = (SmLayout*)smem_raw;

    int b = blockIdx.x / NQ;
    int q = blockIdx.x % NQ;
    int tid = threadIdx.x, lane = tid & 31, wid = tid >> 5;

    unsigned mb0 = smem_u32(&s->mbar[0]);
    unsigned mb1 = smem_u32(&s->mbar[1]);
    unsigned bufaddr0 = smem_u32(&s->buf[0][0]);
    unsigned bufaddr1 = smem_u32(&s->buf[1][0]);

    if (tid == 0){
        mbar_init(mb0, 1);
        mbar_init(mb1, 1);
        s->acc[0] = s->acc[1] = s->acc[2] = s->acc[3] = 0.f;
    }
    // stage bit masks
    for (int i = tid; i < NF*HH*WPR; i += THR) s->tb[i] = g_tbits[b*NF*HH*WPR + i];
    for (int i = tid; i < HH*WPR;    i += THR) s->pb[i] = g_pbits[b*HH*WPR + i];
    __syncthreads();

    const float* base0 = masks + ((size_t)((b*NF+0)*NQ + q))*HW;
    const size_t fstride = (size_t)NQ*HW;

    if (tid == 0){
        mbar_expect_tx(mb0, TILE_BYTES);
        bulk_g2s(bufaddr0, base0,            TILE_BYTES, mb0);
        mbar_expect_tx(mb1, TILE_BYTES);
        bulk_g2s(bufaddr1, base0 + fstride,  TILE_BYTES, mb1);
    }

    int fc = tid % 24;          // float4 column
    int r0 = tid / 24;          // 0..15
    int wi = fc >> 3;
    int shb = (4*fc) & 31;

    float focal = 0.f, thsum = 0.f, thp = 0.f;

    for (int f = 0; f < NF; f++){
        int cb = f & 1;
        mbar_wait(cb ? mb1 : mb0, (f >> 1) & 1);
        __syncthreads();   // all consumers see full buffer; rowpart/colpart free

        const float4* bb = (const float4*)s->buf[cb];
        const unsigned* tbf = &s->tb[f*HH*WPR];

        float c0=-INFINITY, c1=-INFINITY, c2=-INFINITY, c3=-INFINITY;
        #pragma unroll
        for (int k = 0; k < 6; k++){
            int r = r0 + 16*k;
            float4 x4 = bb[r*24 + fc];
            unsigned tw = tbf[r*WPR + wi] >> shb;
            unsigned pw = s->pb[r*WPR + wi] >> shb;
            float rmax = -INFINITY;
            float xs[4] = {x4.x, x4.y, x4.z, x4.w};
            #pragma unroll
            for (int j = 0; j < 4; j++){
                float x = ((pw >> j) & 1u) ? 0.f : xs[j];
                bool tt = (tw >> j) & 1u;
                float th = tanh_approx(0.5f * x);
                thsum += th;
                if (tt) thp += th;
                float sgn = tt ? 0.5f : -0.5f;
                float pt  = fmaf(sgn, th, 0.5f);
                float qv  = 1.f - pt;
                float l   = __log2f(fmaxf(pt, 1e-12f));
                float cf  = tt ? (-0.25f*LN2F) : (-0.75f*LN2F);
                focal = fmaf(cf*l, qv*qv, focal);
                rmax = fmaxf(rmax, x);
                if      (j == 0) c0 = fmaxf(c0, x);
                else if (j == 1) c1 = fmaxf(c1, x);
                else if (j == 2) c2 = fmaxf(c2, x);
                else             c3 = fmaxf(c3, x);
            }
            s->rowpart[r*25 + fc] = rmax;
        }
        ((float4*)s->colpart)[r0*24 + fc] = make_float4(c0, c1, c2, c3);
        __syncthreads();   // compute done; buffer free for reuse; partials ready

        // refill this buffer with tile f+2
        if (tid == 0 && f + 2 < NF){
            unsigned mb = cb ? mb1 : mb0;
            mbar_expect_tx(mb, TILE_BYTES);
            bulk_g2s(cb ? bufaddr1 : bufaddr0, base0 + (size_t)(f+2)*fstride, TILE_BYTES, mb);
        }

        // projection tail for this f
        int bf = b*NF + f;
        float a = 0.f, bs = 0.f;
        if (tid < 96){
            int h = tid; float m = -INFINITY;
            #pragma unroll
            for (int c = 0; c < 24; c++) m = fmaxf(m, s->rowpart[h*25 + c]);
            float sp = sigf(m);
            a = sp; bs = sp * __ldg(&g_tcm[bf*HH + h]);
        } else if (tid < 192){
            int w = tid - 96; float m = -INFINITY;
            #pragma unroll
            for (int g = 0; g < 16; g++) m = fmaxf(m, s->colpart[g*WW + w]);
            float sp = sigf(m);
            a = sp; bs = sp * __ldg(&g_trm[bf*WW + w]);
        }
        if (tid < 192){
            #pragma unroll
            for (int off = 16; off; off >>= 1){
                a  += __shfl_down_sync(0xffffffffu, a,  off);
                bs += __shfl_down_sync(0xffffffffu, bs, off);
            }
            if (lane == 0){ s->red2[wid][0] = a; s->red2[wid][1] = bs; }
        }
        __syncthreads();
        if (tid == 0){
            s->acc[0] += s->red2[0][0] + s->red2[1][0] + s->red2[2][0];  // SX
            s->acc[1] += s->red2[0][1] + s->red2[1][1] + s->red2[2][1];  // STX
            s->acc[2] += s->red2[3][0] + s->red2[4][0] + s->red2[5][0];  // SY
            s->acc[3] += s->red2[3][1] + s->red2[4][1] + s->red2[5][1];  // STY
        }
        __syncthreads();   // protect red2/rowpart/colpart before next f
    }

    // block reduction of focal / thsum / thp (12 warps)
    #pragma unroll
    for (int off = 16; off; off >>= 1){
        focal += __shfl_down_sync(0xffffffffu, focal, off);
        thsum += __shfl_down_sync(0xffffffffu, thsum, off);
        thp   += __shfl_down_sync(0xffffffffu, thp,   off);
    }
    if (lane == 0){ s->red[wid*3] = focal; s->red[wid*3+1] = thsum; s->red[wid*3+2] = thp; }
    __syncthreads();

    // per-(b,q) scalar costs: warp 0, lanes 0..7 handle f=lane
    if (wid == 0){
        float TS=0, TTY=0, TTX=0, wsum=0, cc=0, bbsum=0, gsum=0;
        if (lane < NF){
            int f = lane, bf = b*NF + f;
            TS  = g_tscal[bf*4+0];
            TTY = g_tscal[bf*4+1];
            TTX = g_tscal[bf*4+2];

            float wf = (tvalid[bf] != 0) ? 1.f : 0.f;
            wsum = wf;
            float lg = logits[bf*NQ + q];
            float pp;
            if (lg >= 0.f){ float e = expf(-lg); pp = 1.f/(1.f+e); }
            else          { float e = expf( lg); pp = e/(1.f+e); }
            float pos = 0.25f*(1.f-pp)*(1.f-pp)*(-logf(pp + 1e-8f));
            float neg = 0.75f*pp*pp*(-logf(1.f - pp + 1e-8f));
            cc = (pos - neg)*wf;

            const float* sb = boxes + (size_t)(bf*NQ + q)*4;
            const float* tb = tbox  + (size_t)bf*4;
            float scx=sb[0], scy=sb[1], sw=sb[2], sh=sb[3];
            float tcx=tb[0], tcy=tb[1], tw=tb[2], th=tb[3];
            bbsum = fabsf(scx-tcx) + fabsf(scy-tcy) + fabsf(sw-tw) + fabsf(sh-th);

            float sx0=scx-0.5f*sw, sy0=scy-0.5f*sh, sx1=scx+0.5f*sw, sy1=scy+0.5f*sh;
            float tx0=tcx-0.5f*tw, ty0=tcy-0.5f*th, tx1=tcx+0.5f*tw, ty1=tcy+0.5f*th;
            float a1=(sx1-sx0)*(sy1-sy0);
            float a2=(tx1-tx0)*(ty1-ty0);
            float ltx=fmaxf(sx0,tx0), lty=fmaxf(sy0,ty0);
            float rbx=fminf(sx1,tx1), rby=fminf(sy1,ty1);
            float iw=fmaxf(rbx-ltx,0.f), ih=fmaxf(rby-lty,0.f);
            float inter=iw*ih;
            float uni=a1+a2-inter;
            float iou=inter/uni;
            float cx0=fminf(sx0,tx0), cy0=fminf(sy0,ty0);
            float cx1=fmaxf(sx1,tx1), cy1=fmaxf(sy1,ty1);
            float cw=fmaxf(cx1-cx0,0.f), ch=fmaxf(cy1-cy0,0.f);
            float ac=cw*ch;
            gsum = iou - (ac-uni)/ac;
        }
        #pragma unroll
        for (int off = 4; off; off >>= 1){
            TS    += __shfl_down_sync(0xffffffffu, TS,    off);
            TTY   += __shfl_down_sync(0xffffffffu, TTY,   off);
            TTX   += __shfl_down_sync(0xffffffffu, TTX,   off);
            wsum  += __shfl_down_sync(0xffffffffu, wsum,  off);
            cc    += __shfl_down_sync(0xffffffffu, cc,    off);
            bbsum += __shfl_down_sync(0xffffffffu, bbsum, off);
            gsum  += __shfl_down_sync(0xffffffffu, gsum,  off);
        }
        if (lane == 0){
            float F=0, TH=0, TP=0;
            #pragma unroll
            for (int w = 0; w < 12; w++){ F += s->red[w*3]; TH += s->red[w*3+1]; TP += s->red[w*3+2]; }
            float S  = 0.5f*(float)DTOT + 0.5f*TH;
            float ST = 0.5f*TS + 0.5f*TP;
            float cost_mask = F / (float)DTOT;
            float cost_dice = -(2.f*ST + 1.f) / (S + TS + 1.f);
            float cost_proj = -0.5f * ( (2.f*s->acc[1] + 1.f)/(s->acc[0] + TTX + 1.f)
                                      + (2.f*s->acc[3] + 1.f)/(s->acc[2] + TTY + 1.f) );
            outf[b*NQ + q] = cc/wsum + bbsum/(float)NF - gsum/(float)NF
                           + cost_mask + cost_dice + cost_proj;
            __threadfence();
            unsigned prev = atomicAdd(&g_count, 1u);
            s->isLast = (prev == (unsigned)(NBQ - 1));
        }
    }
    __syncthreads();
    if (!s->isLast) return;
    __threadfence();

    // ---------------- last-block argmin over outf[0..599] ----------------
    for (int b2 = 0; b2 < BS; b2++){
        float v = (tid < NQ) ? outf[b2*NQ + tid] : INFINITY;
        int idx = tid;
        #pragma unroll
        for (int off = 16; off; off >>= 1){
            float v2 = __shfl_down_sync(0xffffffffu, v, off);
            int   i2 = __shfl_down_sync(0xffffffffu, idx, off);
            if (v2 < v || (v2 == v && i2 < idx)){ v = v2; idx = i2; }
        }
        if (lane == 0){ s->avm[wid] = v; s->aim[wid] = idx; }
        __syncthreads();
        if (tid == 0){
            float bv = s->avm[0]; int bi = s->aim[0];
            #pragma unroll
            for (int w = 1; w < 12; w++){
                if (s->avm[w] < bv || (s->avm[w] == bv && s->aim[w] < bi)){ bv = s->avm[w]; bi = s->aim[w]; }
            }
            if (out_size == 608){
                long long* ip = (long long*)(outf + BS*NQ);
                ip[b2]      = (long long)bi;
                ip[BS + b2] = 0LL;
            } else if (out_size >= BS*NQ + 2*BS){
                outf[BS*NQ + b2]      = (float)bi;
                outf[BS*NQ + BS + b2] = 0.f;
            }
        }
        __syncthreads();
    }
    if (tid == 0) g_count = 0;   // reset for next graph replay
}

// ---------------- launch ----------------
extern "C" void kernel_launch(void* const* d_in, const int* in_sizes, int n_in,
                              void* d_out, int out_size)
{
    const float* logits = (const float*)d_in[0];
    const float* boxes  = (const float*)d_in[1];
    const float* masks  = (const float*)d_in[2];
    const float* tmask  = (const float*)d_in[3];
    const float* tbox   = (const float*)d_in[4];
    const int*   tvalid = (const int*)d_in[5];
    const unsigned char* pad = (const unsigned char*)d_in[6];
    float* outf = (float*)d_out;

    cudaFuncSetAttribute(main_kernel, cudaFuncAttributeMaxDynamicSharedMemorySize,
                         (int)sizeof(SmLayout));

    tgt_kernel <<<BS*NF, 256>>>(tmask, pad);
    main_kernel<<<NBQ,   THR, sizeof(SmLayout)>>>(masks, logits, boxes, tbox, tvalid, outf, out_size);
}